// round 9
// baseline (speedup 1.0000x reference)
#include <cuda_runtime.h>
#include <math.h>

// Problem constants
#define BATCH 8
#define LSEQ  1024
#define DMODEL 1024
#define NHEAD 16
#define DK 64

// ---------------------------------------------------------------------------
// Scratch: one big __device__ global (allocation APIs are forbidden).
// Layout (floats):
//   [0,1M)    WQ   reshaped w_qs  (1024 x 1024 row-major, col = h*64+k)
//   [1M,2M)   WK
//   [2M,3M)   WV
//   [3M,4M)   WPT  proj_w transposed (j,m)
//   [4M,12M)  QS   q_s  (8192 x 1024)
//   [12M,20M) KS   k_s
//   [20M,28M) VS   v_s
//   [28M,36M) CTX  concat heads (8192 x 1024)
// ---------------------------------------------------------------------------
#define M1 (1024u*1024u)
__device__ float g_scratch[36u * M1];

// ---------------- f32x2 helpers (FFMA2 is PTX-only on sm_103a) -------------
__device__ __forceinline__ unsigned long long pk2(float a, float b) {
    unsigned long long o;
    asm("mov.b64 %0, {%1, %2};" : "=l"(o)
        : "r"(__float_as_uint(a)), "r"(__float_as_uint(b)));
    return o;
}
__device__ __forceinline__ void fma2(unsigned long long& d,
                                     unsigned long long a,
                                     unsigned long long b) {
    asm("fma.rn.f32x2 %0, %1, %2, %0;" : "+l"(d) : "l"(a), "l"(b));
}
__device__ __forceinline__ float2 upk2(unsigned long long v) {
    unsigned int lo, hi;
    asm("mov.b64 {%0, %1}, %2;" : "=r"(lo), "=r"(hi) : "l"(v));
    return make_float2(__uint_as_float(lo), __uint_as_float(hi));
}

// ---------------------------------------------------------------------------
// Weight reshapes
// ---------------------------------------------------------------------------
// o[d*1024 + (h*64+k)] = w[h*65536 + d*64 + k]
__global__ void reshape_qkv_w(const float* __restrict__ w, float* __restrict__ o) {
    int i = blockIdx.x * 256 + threadIdx.x;   // 1M elements
    int d = i >> 10;
    int c = i & 1023;
    o[i] = w[((c >> 6) << 16) + (d << 6) + (c & 63)];
}

// o[j*1024 + m] = w[m*1024 + j]
__global__ void transpose_1024(const float* __restrict__ w, float* __restrict__ o) {
    __shared__ float tile[32][33];
    int bx = blockIdx.x * 32, by = blockIdx.y * 32;
    int tx = threadIdx.x, ty = threadIdx.y;   // block (32,8)
    for (int r = ty; r < 32; r += 8)
        tile[r][tx] = w[(size_t)(by + r) * 1024 + bx + tx];
    __syncthreads();
    for (int r = ty; r < 32; r += 8)
        o[(size_t)(bx + r) * 1024 + by + tx] = tile[tx][r];
}

// ---------------------------------------------------------------------------
// SGEMM 128x128x16, 256 threads, 8x8 per thread, double-buffered, f32x2 FMA.
// A: M x K row-major, B: K x N row-major, C: M x N. Fixed M=8192,N=1024,K=1024.
// EPI==1: C = acc + bias[col] + resid[row,col]
// ---------------------------------------------------------------------------
template <int EPI>
__global__ __launch_bounds__(256, 2)
void sgemm_kernel(const float* __restrict__ A, const float* __restrict__ B,
                  float* __restrict__ C,
                  const float* __restrict__ bias, const float* __restrict__ resid) {
    const int K = 1024, N = 1024;
    __shared__ float As[2][16][128];
    __shared__ float Bs[2][16][128];

    const int t  = threadIdx.x;
    const int bx = blockIdx.x, by = blockIdx.y;
    const int aRow = t >> 2;            // 0..63
    const int aCol = (t & 3) << 2;      // 0,4,8,12
    const int bRow = t >> 5;            // 0..7
    const int bCol = (t & 31) << 2;     // 0..124
    const int tx = t & 15, ty = t >> 4;

    const float* Ap = A + (size_t)(by * 128 + aRow) * K + aCol;
    const float* Bp = B + (size_t)bRow * N + bx * 128 + bCol;

    unsigned long long acc[8][4];
#pragma unroll
    for (int i = 0; i < 8; i++)
#pragma unroll
        for (int j = 0; j < 4; j++) acc[i][j] = 0ull;

    float4 a0 = *(const float4*)(Ap);
    float4 a1 = *(const float4*)(Ap + (size_t)64 * K);
    float4 b0 = *(const float4*)(Bp);
    float4 b1 = *(const float4*)(Bp + (size_t)8 * N);

    int buf = 0;
    // store tile 0 (A transposed into [k][m])
    As[0][aCol + 0][aRow] = a0.x; As[0][aCol + 1][aRow] = a0.y;
    As[0][aCol + 2][aRow] = a0.z; As[0][aCol + 3][aRow] = a0.w;
    As[0][aCol + 0][aRow + 64] = a1.x; As[0][aCol + 1][aRow + 64] = a1.y;
    As[0][aCol + 2][aRow + 64] = a1.z; As[0][aCol + 3][aRow + 64] = a1.w;
    *(float4*)&Bs[0][bRow][bCol]     = b0;
    *(float4*)&Bs[0][bRow + 8][bCol] = b1;
    __syncthreads();

    for (int kt = 16; kt <= K; kt += 16) {
        const bool has_next = (kt < K);
        if (has_next) {
            a0 = *(const float4*)(Ap + kt);
            a1 = *(const float4*)(Ap + (size_t)64 * K + kt);
            b0 = *(const float4*)(Bp + (size_t)kt * N);
            b1 = *(const float4*)(Bp + (size_t)(kt + 8) * N);
        }
#pragma unroll
        for (int kk = 0; kk < 16; kk++) {
            float4 av0 = *(const float4*)&As[buf][kk][ty * 8];
            float4 av1 = *(const float4*)&As[buf][kk][ty * 8 + 4];
            float4 bv0 = *(const float4*)&Bs[buf][kk][tx * 8];
            float4 bv1 = *(const float4*)&Bs[buf][kk][tx * 8 + 4];
            unsigned long long bd[4];
            bd[0] = pk2(bv0.x, bv0.y); bd[1] = pk2(bv0.z, bv0.w);
            bd[2] = pk2(bv1.x, bv1.y); bd[3] = pk2(bv1.z, bv1.w);
            float a8[8] = {av0.x, av0.y, av0.z, av0.w, av1.x, av1.y, av1.z, av1.w};
#pragma unroll
            for (int i = 0; i < 8; i++) {
                unsigned long long ad = pk2(a8[i], a8[i]);
#pragma unroll
                for (int j = 0; j < 4; j++) fma2(acc[i][j], ad, bd[j]);
            }
        }
        if (has_next) {
            buf ^= 1;
            As[buf][aCol + 0][aRow] = a0.x; As[buf][aCol + 1][aRow] = a0.y;
            As[buf][aCol + 2][aRow] = a0.z; As[buf][aCol + 3][aRow] = a0.w;
            As[buf][aCol + 0][aRow + 64] = a1.x; As[buf][aCol + 1][aRow + 64] = a1.y;
            As[buf][aCol + 2][aRow + 64] = a1.z; As[buf][aCol + 3][aRow + 64] = a1.w;
            *(float4*)&Bs[buf][bRow][bCol]     = b0;
            *(float4*)&Bs[buf][bRow + 8][bCol] = b1;
            __syncthreads();
        }
    }

    const int row0 = by * 128 + ty * 8;
    const int col0 = bx * 128 + tx * 8;
#pragma unroll
    for (int i = 0; i < 8; i++) {
#pragma unroll
        for (int j = 0; j < 4; j++) {
            float2 v = upk2(acc[i][j]);
            size_t idx = (size_t)(row0 + i) * N + col0 + j * 2;
            if (EPI) {
                v.x += bias[col0 + j * 2]     + resid[idx];
                v.y += bias[col0 + j * 2 + 1] + resid[idx + 1];
            }
            *(float2*)&C[idx] = v;
        }
    }
}

// ---------------------------------------------------------------------------
// Fused attention: per (h, b, 32-row q tile).
// S tile (32 x 1024) lives in smem; softmax in smem; attn written to d_out;
// P @ V accumulated from smem (attn never re-read from HBM).
// smem: Ss 32x1025 + Qs 32x64 + KV 128x65  = 172672 B
// ---------------------------------------------------------------------------
#define TQ 32
#define TKC 128
#define LP (LSEQ + 1)
#define ATTN_SMEM ((TQ * LP + TQ * DK + TKC * 65) * 4)

__global__ __launch_bounds__(256, 1)
void attn_kernel(const float* __restrict__ qs, const float* __restrict__ ks,
                 const float* __restrict__ vs, const unsigned char* __restrict__ mask,
                 float* __restrict__ attn_out, float* __restrict__ ctx) {
    extern __shared__ float sm[];
    float* Ss = sm;                    // TQ x LP
    float* Qs = Ss + TQ * LP;          // TQ x DK
    float* KV = Qs + TQ * DK;          // TKC x 65

    const int h = blockIdx.z, b = blockIdx.y;
    const int q0 = blockIdx.x * TQ;
    const int t = threadIdx.x;
    const int hd = h * DK;
    const float inv_temper = 1.0f / 32.0f;   // 1/sqrt(D_MODEL)
    const float NEG_INF = __int_as_float(0xff800000);

    // load Q tile
    {
        int r = t >> 4;
        int c4 = (t & 15) << 2;
#pragma unroll
        for (int rep = 0; rep < 2; rep++) {
            int rr = r + rep * 16;
            float4 v = *(const float4*)(qs + ((size_t)(b * LSEQ + q0 + rr)) * 1024 + hd + c4);
            *(float4*)&Qs[rr * DK + c4] = v;
        }
    }

    const int tr = t >> 5;   // warp id 0..7 -> rows 4*tr..4*tr+3
    const int tc = t & 31;   // lane

    // ---- S = (Q K^T) / temper, key chunks of 128 ----
    for (int kk0 = 0; kk0 < LSEQ; kk0 += TKC) {
        __syncthreads();   // Qs ready (iter 0) / previous KV readers done
        {
            int lk = t >> 4;
            int c4 = (t & 15) << 2;
#pragma unroll
            for (int rep = 0; rep < 8; rep++) {
                int kkl = lk + rep * 16;
                float4 v = *(const float4*)(ks + ((size_t)(b * LSEQ + kk0 + kkl)) * 1024 + hd + c4);
                KV[kkl * 65 + c4 + 0] = v.x;
                KV[kkl * 65 + c4 + 1] = v.y;
                KV[kkl * 65 + c4 + 2] = v.z;
                KV[kkl * 65 + c4 + 3] = v.w;
            }
        }
        __syncthreads();
        float acc[4][4] = {};
#pragma unroll
        for (int d = 0; d < DK; d++) {
            float qv[4], kv[4];
#pragma unroll
            for (int i = 0; i < 4; i++) qv[i] = Qs[(tr * 4 + i) * DK + d];
#pragma unroll
            for (int j = 0; j < 4; j++) kv[j] = KV[(tc + 32 * j) * 65 + d];
#pragma unroll
            for (int i = 0; i < 4; i++)
#pragma unroll
                for (int j = 0; j < 4; j++) acc[i][j] += qv[i] * kv[j];
        }
#pragma unroll
        for (int i = 0; i < 4; i++)
#pragma unroll
            for (int j = 0; j < 4; j++)
                Ss[(tr * 4 + i) * LP + kk0 + tc + 32 * j] = acc[i][j] * inv_temper;
    }
    __syncthreads();

    // ---- mask + softmax (each warp owns its 4 rows) + write attn out ----
    {
        const int lane = tc;
        const unsigned char* mbase = mask + ((size_t)b * LSEQ + q0) * LSEQ;
#pragma unroll
        for (int i = 0; i < 4; i++) {
            int r = tr * 4 + i;
            float* srow = Ss + r * LP;
            const unsigned char* mr = mbase + (size_t)r * LSEQ;
            float m = NEG_INF;
            for (int c = lane; c < LSEQ; c += 32) {
                float v = srow[c];
                if (mr[c]) { v = NEG_INF; srow[c] = v; }
                m = fmaxf(m, v);
            }
#pragma unroll
            for (int o = 16; o > 0; o >>= 1) m = fmaxf(m, __shfl_xor_sync(0xffffffffu, m, o));
            float s = 0.0f;
            for (int c = lane; c < LSEQ; c += 32) {
                float p = __expf(srow[c] - m);
                srow[c] = p;
                s += p;
            }
#pragma unroll
            for (int o = 16; o > 0; o >>= 1) s += __shfl_xor_sync(0xffffffffu, s, o);
            float inv = 1.0f / s;
            float* arow = attn_out + (((size_t)(h * BATCH + b)) * LSEQ + q0 + r) * LSEQ;
            for (int c = lane; c < LSEQ; c += 32) {
                float p = srow[c] * inv;
                srow[c] = p;
                arow[c] = p;
            }
        }
    }
    __syncthreads();

    // ---- O = P @ V, key chunks of 128 ----
    float oacc[4][2] = {};
    for (int kk0 = 0; kk0 < LSEQ; kk0 += TKC) {
        __syncthreads();
        {
            int lk = t >> 4;
            int c4 = (t & 15) << 2;
#pragma unroll
            for (int rep = 0; rep < 8; rep++) {
                int kkl = lk + rep * 16;
                float4 v = *(const float4*)(vs + ((size_t)(b * LSEQ + kk0 + kkl)) * 1024 + hd + c4);
                KV[kkl * 65 + c4 + 0] = v.x;
                KV[kkl * 65 + c4 + 1] = v.y;
                KV[kkl * 65 + c4 + 2] = v.z;
                KV[kkl * 65 + c4 + 3] = v.w;
            }
        }
        __syncthreads();
#pragma unroll 4
        for (int kk = 0; kk < TKC; kk++) {
            float pv[4], vv[2];
#pragma unroll
            for (int i = 0; i < 4; i++) pv[i] = Ss[(tr * 4 + i) * LP + kk0 + kk];
            vv[0] = KV[kk * 65 + tc];
            vv[1] = KV[kk * 65 + tc + 32];
#pragma unroll
            for (int i = 0; i < 4; i++) {
                oacc[i][0] += pv[i] * vv[0];
                oacc[i][1] += pv[i] * vv[1];
            }
        }
    }
#pragma unroll
    for (int i = 0; i < 4; i++) {
        size_t base = ((size_t)(b * LSEQ + q0 + tr * 4 + i)) * 1024 + hd;
        ctx[base + tc]      = oacc[i][0];
        ctx[base + tc + 32] = oacc[i][1];
    }
}

// ---------------------------------------------------------------------------
// In-place LayerNorm over rows of 1024 (biased variance, eps=1e-5)
// ---------------------------------------------------------------------------
__global__ void ln_kernel(float* __restrict__ y,
                          const float* __restrict__ gamma,
                          const float* __restrict__ beta) {
    __shared__ float red[18];
    const int row = blockIdx.x;
    const int t = threadIdx.x;     // 256
    float* p = y + (size_t)row * 1024;
    float v[4];
    float s = 0.0f, s2 = 0.0f;
#pragma unroll
    for (int j = 0; j < 4; j++) {
        v[j] = p[t + 256 * j];
        s += v[j];
        s2 += v[j] * v[j];
    }
#pragma unroll
    for (int o = 16; o > 0; o >>= 1) {
        s  += __shfl_xor_sync(0xffffffffu, s, o);
        s2 += __shfl_xor_sync(0xffffffffu, s2, o);
    }
    int warp = t >> 5, lane = t & 31;
    if (lane == 0) { red[warp] = s; red[8 + warp] = s2; }
    __syncthreads();
    if (t == 0) {
        float a = 0.0f, bsum = 0.0f;
#pragma unroll
        for (int w = 0; w < 8; w++) { a += red[w]; bsum += red[8 + w]; }
        red[16] = a; red[17] = bsum;
    }
    __syncthreads();
    float mean = red[16] * (1.0f / 1024.0f);
    float var  = red[17] * (1.0f / 1024.0f) - mean * mean;
    float inv  = rsqrtf(var + 1e-5f);
#pragma unroll
    for (int j = 0; j < 4; j++) {
        int c = t + 256 * j;
        p[c] = (v[j] - mean) * inv * gamma[c] + beta[c];
    }
}

// ---------------------------------------------------------------------------
// kernel_launch
// Inputs (metadata order): q, k, v, attn_mask(bool), w_qs, w_ks, w_vs,
//                          proj_w, proj_b, ln_gamma, ln_beta
// d_out: [outputs (8192*1024 f32)] [attns (128*1024*1024 f32)]
// ---------------------------------------------------------------------------
extern "C" void kernel_launch(void* const* d_in, const int* in_sizes, int n_in,
                              void* d_out, int out_size) {
    const float* q       = (const float*)d_in[0];
    const float* k       = (const float*)d_in[1];
    const float* v       = (const float*)d_in[2];
    const unsigned char* mask = (const unsigned char*)d_in[3];
    const float* w_qs    = (const float*)d_in[4];
    const float* w_ks    = (const float*)d_in[5];
    const float* w_vs    = (const float*)d_in[6];
    const float* proj_w  = (const float*)d_in[7];
    const float* proj_b  = (const float*)d_in[8];
    const float* gamma   = (const float*)d_in[9];
    const float* beta    = (const float*)d_in[10];

    float* out = (float*)d_out;
    float* attn_out = out + (size_t)8192 * 1024;

    float* S = nullptr;
    cudaGetSymbolAddress((void**)&S, g_scratch);
    float* WQ  = S;
    float* WK  = S + 1 * M1;
    float* WV  = S + 2 * M1;
    float* WPT = S + 3 * M1;
    float* QS  = S + 4 * (size_t)M1;
    float* KS  = S + 12 * (size_t)M1;
    float* VS  = S + 20 * (size_t)M1;
    float* CTX = S + 28 * (size_t)M1;

    // weight reshapes
    reshape_qkv_w<<<4096, 256>>>(w_qs, WQ);
    reshape_qkv_w<<<4096, 256>>>(w_ks, WK);
    reshape_qkv_w<<<4096, 256>>>(w_vs, WV);
    transpose_1024<<<dim3(32, 32), dim3(32, 8)>>>(proj_w, WPT);

    // QKV projections (8192x1024x1024 each)
    dim3 gg(8, 64);
    sgemm_kernel<0><<<gg, 256>>>(q, WQ, QS, nullptr, nullptr);
    sgemm_kernel<0><<<gg, 256>>>(k, WK, KS, nullptr, nullptr);
    sgemm_kernel<0><<<gg, 256>>>(v, WV, VS, nullptr, nullptr);

    // fused attention (writes attn_out + CTX)
    cudaFuncSetAttribute(attn_kernel, cudaFuncAttributeMaxDynamicSharedMemorySize, ATTN_SMEM);
    attn_kernel<<<dim3(LSEQ / TQ, BATCH, NHEAD), 256, ATTN_SMEM>>>(QS, KS, VS, mask, attn_out, CTX);

    // output projection + bias + residual, then in-place LayerNorm
    sgemm_kernel<1><<<gg, 256>>>(CTX, WPT, out, proj_b, q);
    ln_kernel<<<8192, 256>>>(out, gamma, beta);
}

// round 12
// speedup vs baseline: 1.3743x; 1.3743x over previous
#include <cuda_runtime.h>
#include <cuda_bf16.h>
#include <math.h>
#include <stdint.h>

// Problem constants
#define BATCH 8
#define LSEQ  1024
#define DMODEL 1024
#define NHEAD 16
#define DK 64

// ---------------------------------------------------------------------------
// Scratch (__device__ globals; allocation APIs forbidden)
//   g_f32 : QS[8M] KS[8M] VS[8M] CTX[8M] floats
//   g_wbf : WQh WQl WKh WKl WVh WVl WPh WPl (1M bf16 each), [N,K] row-major
// ---------------------------------------------------------------------------
#define M1 (1024u*1024u)
__device__ float          g_f32[(size_t)32 * M1];
__device__ __nv_bfloat16  g_wbf[(size_t)8  * M1];

// ======================= helpers ===========================================
__device__ __forceinline__ uint32_t smem_u32(const void* p) {
    uint32_t a;
    asm("{ .reg .u64 t; cvta.to.shared.u64 t, %1; cvt.u32.u64 %0, t; }"
        : "=r"(a) : "l"(p));
    return a;
}
__device__ __forceinline__ void ldsm4(uint32_t* r, uint32_t addr) {
    asm volatile("ldmatrix.sync.aligned.m8n8.x4.shared.b16 {%0,%1,%2,%3}, [%4];"
                 : "=r"(r[0]), "=r"(r[1]), "=r"(r[2]), "=r"(r[3]) : "r"(addr));
}
__device__ __forceinline__ void mma16816(float* d, const uint32_t* a, const uint32_t* b) {
    asm volatile(
        "mma.sync.aligned.m16n8k16.row.col.f32.bf16.bf16.f32 "
        "{%0,%1,%2,%3}, {%4,%5,%6,%7}, {%8,%9}, {%0,%1,%2,%3};"
        : "+f"(d[0]), "+f"(d[1]), "+f"(d[2]), "+f"(d[3])
        : "r"(a[0]), "r"(a[1]), "r"(a[2]), "r"(a[3]), "r"(b[0]), "r"(b[1]));
}
// split 4 floats into packed bf16 hi (2x u32? -> 2 u32 of 2 bf16) and lo
__device__ __forceinline__ void split4(float4 v, uint32_t& h0, uint32_t& h1,
                                       uint32_t& l0, uint32_t& l1) {
    __nv_bfloat162 ha = __floats2bfloat162_rn(v.x, v.y);
    __nv_bfloat162 hb = __floats2bfloat162_rn(v.z, v.w);
    float lx = v.x - __bfloat162float(ha.x);
    float ly = v.y - __bfloat162float(ha.y);
    float lz = v.z - __bfloat162float(hb.x);
    float lw = v.w - __bfloat162float(hb.y);
    __nv_bfloat162 la = __floats2bfloat162_rn(lx, ly);
    __nv_bfloat162 lb = __floats2bfloat162_rn(lz, lw);
    h0 = (uint32_t)__bfloat16_as_ushort(ha.x) | ((uint32_t)__bfloat16_as_ushort(ha.y) << 16);
    h1 = (uint32_t)__bfloat16_as_ushort(hb.x) | ((uint32_t)__bfloat16_as_ushort(hb.y) << 16);
    l0 = (uint32_t)__bfloat16_as_ushort(la.x) | ((uint32_t)__bfloat16_as_ushort(la.y) << 16);
    l1 = (uint32_t)__bfloat16_as_ushort(lb.x) | ((uint32_t)__bfloat16_as_ushort(lb.y) << 16);
}

// ======================= weight prep kernels ================================
// w_qs[h][d][kk] -> B^T[n=h*64+kk][k=d] bf16 hi/lo
__global__ void reshape_split_qkv(const float* __restrict__ w,
                                  __nv_bfloat16* __restrict__ hi,
                                  __nv_bfloat16* __restrict__ lo) {
    int i = blockIdx.x * 256 + threadIdx.x;   // 1M elements
    int n = i >> 10;
    int d = i & 1023;
    float v = w[((n >> 6) << 16) + (d << 6) + (n & 63)];
    __nv_bfloat16 h = __float2bfloat16(v);
    hi[i] = h;
    lo[i] = __float2bfloat16(v - __bfloat162float(h));
}
// proj_w is already [N,K] row-major; plain split
__global__ void split_bf16_kernel(const float4* __restrict__ x,
                                  uint2* __restrict__ hi, uint2* __restrict__ lo, int n4) {
    int i = blockIdx.x * 256 + threadIdx.x;
    if (i >= n4) return;
    uint32_t h0, h1, l0, l1;
    split4(x[i], h0, h1, l0, l1);
    hi[i] = make_uint2(h0, h1);
    lo[i] = make_uint2(l0, l1);
}

// ======================= mma.sync split-bf16 GEMM ===========================
// C[8192,1024] = A[8192,1024](fp32, converted inline) * B^T (bf16 hi/lo [N,K])
// acc = Ah*Bh + Ah*Bl + Al*Bh.  CTA 128x128, K-chunk 32, double-buffered smem.
// EPI==1: += bias[col] + resid[row,col]
#define GSTRIDE 80                 // padded smem row stride (bytes)
#define TILE_B  (128 * GSTRIDE)    // 10240
#define STAGE_B (4 * TILE_B)       // Ah Al Bh Bl
#define GEMM_SMEM (2 * STAGE_B)    // 81920

template <int EPI>
__global__ __launch_bounds__(256, 1)
void gemm_mma_kernel(const float* __restrict__ A,
                     const __nv_bfloat16* __restrict__ Bh,
                     const __nv_bfloat16* __restrict__ Bl,
                     float* __restrict__ C,
                     const float* __restrict__ bias,
                     const float* __restrict__ resid) {
    extern __shared__ __align__(128) char sm[];
    const int t = threadIdx.x;
    const int bx = blockIdx.x, by = blockIdx.y;
    const int wid = t >> 5, lane = t & 31;

    const float* Abase = A + (size_t)(by * 128) * 1024;
    const __nv_bfloat16* Bhb = Bh + (size_t)(bx * 128) * 1024;
    const __nv_bfloat16* Blb = Bl + (size_t)(bx * 128) * 1024;

    float4 ar[4];
    uint4  bhr[2], blr[2];

    const uint32_t smb = smem_u32(sm);
    const int wm = wid & 3;      // M warp (4 x 32 rows)
    const int wn = wid >> 2;     // N warp (2 x 64 cols)

    float acc[2][8][4];
#pragma unroll
    for (int mt = 0; mt < 2; mt++)
#pragma unroll
        for (int nt = 0; nt < 8; nt++)
#pragma unroll
            for (int j = 0; j < 4; j++) acc[mt][nt][j] = 0.0f;

    // ldmatrix base byte-offsets (within tile, k-offset added later)
    const uint32_t aoff = (uint32_t)((wm * 32 + (lane & 15)) * GSTRIDE + (lane >> 4) * 16);
    const uint32_t boff = (uint32_t)((wn * 64 + (lane & 7) + ((lane >> 4) & 1) * 8) * GSTRIDE
                                     + ((lane >> 3) & 1) * 16);

#define LOAD_REGS(k0)                                                         \
    {                                                                         \
        _Pragma("unroll")                                                     \
        for (int i = 0; i < 4; i++) {                                         \
            int idx = t + 256 * i, row = idx >> 3, seg = idx & 7;             \
            ar[i] = *(const float4*)(Abase + (size_t)row * 1024 + (k0) + seg * 4); \
        }                                                                     \
        _Pragma("unroll")                                                     \
        for (int i = 0; i < 2; i++) {                                         \
            int idx = t + 256 * i, row = idx >> 2, seg = idx & 3;             \
            const char* ph = (const char*)(Bhb + (size_t)row * 1024 + (k0)) + seg * 16; \
            const char* pl = (const char*)(Blb + (size_t)row * 1024 + (k0)) + seg * 16; \
            bhr[i] = *(const uint4*)ph;                                       \
            blr[i] = *(const uint4*)pl;                                       \
        }                                                                     \
    }

#define STORE_SMEM(buf)                                                      \
    {                                                                         \
        char* AH = sm + (buf) * STAGE_B;                                      \
        char* AL = AH + TILE_B;                                               \
        char* BHs = AH + 2 * TILE_B;                                          \
        char* BLs = AH + 3 * TILE_B;                                          \
        _Pragma("unroll")                                                     \
        for (int i = 0; i < 4; i++) {                                         \
            int idx = t + 256 * i, row = idx >> 3, seg = idx & 7;             \
            uint32_t h0, h1, l0, l1;                                          \
            split4(ar[i], h0, h1, l0, l1);                                    \
            *(uint2*)(AH + row * GSTRIDE + seg * 8) = make_uint2(h0, h1);     \
            *(uint2*)(AL + row * GSTRIDE + seg * 8) = make_uint2(l0, l1);     \
        }                                                                     \
        _Pragma("unroll")                                                     \
        for (int i = 0; i < 2; i++) {                                         \
            int idx = t + 256 * i, row = idx >> 2, seg = idx & 3;             \
            *(uint4*)(BHs + row * GSTRIDE + seg * 16) = bhr[i];               \
            *(uint4*)(BLs + row * GSTRIDE + seg * 16) = blr[i];               \
        }                                                                     \
    }

    LOAD_REGS(0);
    STORE_SMEM(0);
    __syncthreads();

    for (int c = 0; c < 32; c++) {
        const int buf = c & 1;
        if (c + 1 < 32) LOAD_REGS((c + 1) * 32);

        const uint32_t AHb = smb + buf * STAGE_B;
        const uint32_t ALb = AHb + TILE_B;
        const uint32_t BHt = AHb + 2 * TILE_B;
        const uint32_t BLt = AHb + 3 * TILE_B;
#pragma unroll
        for (int ks = 0; ks < 2; ks++) {
            const uint32_t kb = ks * 32;
            uint32_t ah[2][4], al[2][4], bh[8][2], bl[8][2];
#pragma unroll
            for (int mt = 0; mt < 2; mt++) {
                ldsm4(ah[mt], AHb + aoff + mt * 16 * GSTRIDE + kb);
                ldsm4(al[mt], ALb + aoff + mt * 16 * GSTRIDE + kb);
            }
#pragma unroll
            for (int p = 0; p < 4; p++) {
                uint32_t r[4];
                ldsm4(r, BHt + boff + p * 16 * GSTRIDE + kb);
                bh[2 * p][0] = r[0]; bh[2 * p][1] = r[1];
                bh[2 * p + 1][0] = r[2]; bh[2 * p + 1][1] = r[3];
                ldsm4(r, BLt + boff + p * 16 * GSTRIDE + kb);
                bl[2 * p][0] = r[0]; bl[2 * p][1] = r[1];
                bl[2 * p + 1][0] = r[2]; bl[2 * p + 1][1] = r[3];
            }
#pragma unroll
            for (int mt = 0; mt < 2; mt++)
#pragma unroll
                for (int nt = 0; nt < 8; nt++) {
                    mma16816(acc[mt][nt], ah[mt], bh[nt]);
                    mma16816(acc[mt][nt], ah[mt], bl[nt]);
                    mma16816(acc[mt][nt], al[mt], bh[nt]);
                }
        }
        if (c + 1 < 32) {
            STORE_SMEM(buf ^ 1);
            __syncthreads();
        }
    }

    // epilogue: d frag mapping r0 = lane>>2 (+8), c0 = (lane&3)*2 (+1)
    const int r0 = lane >> 2, c0 = (lane & 3) * 2;
#pragma unroll
    for (int mt = 0; mt < 2; mt++)
#pragma unroll
        for (int nt = 0; nt < 8; nt++)
#pragma unroll
            for (int half = 0; half < 2; half++) {
                int row = by * 128 + wm * 32 + mt * 16 + r0 + half * 8;
                int col = bx * 128 + wn * 64 + nt * 8 + c0;
                float2 v = make_float2(acc[mt][nt][half * 2], acc[mt][nt][half * 2 + 1]);
                size_t idx = (size_t)row * 1024 + col;
                if (EPI) {
                    v.x += bias[col]     + resid[idx];
                    v.y += bias[col + 1] + resid[idx + 1];
                }
                *(float2*)(C + idx) = v;
            }
}

// ---------------------------------------------------------------------------
// Fused attention (unchanged from passing R9 kernel)
// ---------------------------------------------------------------------------
#define TQ 32
#define TKC 128
#define LP (LSEQ + 1)
#define ATTN_SMEM ((TQ * LP + TQ * DK + TKC * 65) * 4)

__global__ __launch_bounds__(256, 1)
void attn_kernel(const float* __restrict__ qs, const float* __restrict__ ks,
                 const float* __restrict__ vs, const unsigned char* __restrict__ mask,
                 float* __restrict__ attn_out, float* __restrict__ ctx) {
    extern __shared__ float smf[];
    float* Ss = smf;                   // TQ x LP
    float* Qs = Ss + TQ * LP;          // TQ x DK
    float* KV = Qs + TQ * DK;          // TKC x 65

    const int h = blockIdx.z, b = blockIdx.y;
    const int q0 = blockIdx.x * TQ;
    const int t = threadIdx.x;
    const int hd = h * DK;
    const float inv_temper = 1.0f / 32.0f;   // 1/sqrt(D_MODEL)
    const float NEG_INF = __int_as_float(0xff800000);

    {
        int r = t >> 4;
        int c4 = (t & 15) << 2;
#pragma unroll
        for (int rep = 0; rep < 2; rep++) {
            int rr = r + rep * 16;
            float4 v = *(const float4*)(qs + ((size_t)(b * LSEQ + q0 + rr)) * 1024 + hd + c4);
            *(float4*)&Qs[rr * DK + c4] = v;
        }
    }

    const int tr = t >> 5;
    const int tc = t & 31;

    for (int kk0 = 0; kk0 < LSEQ; kk0 += TKC) {
        __syncthreads();
        {
            int lk = t >> 4;
            int c4 = (t & 15) << 2;
#pragma unroll
            for (int rep = 0; rep < 8; rep++) {
                int kkl = lk + rep * 16;
                float4 v = *(const float4*)(ks + ((size_t)(b * LSEQ + kk0 + kkl)) * 1024 + hd + c4);
                KV[kkl * 65 + c4 + 0] = v.x;
                KV[kkl * 65 + c4 + 1] = v.y;
                KV[kkl * 65 + c4 + 2] = v.z;
                KV[kkl * 65 + c4 + 3] = v.w;
            }
        }
        __syncthreads();
        float acc[4][4] = {};
#pragma unroll
        for (int d = 0; d < DK; d++) {
            float qv[4], kv[4];
#pragma unroll
            for (int i = 0; i < 4; i++) qv[i] = Qs[(tr * 4 + i) * DK + d];
#pragma unroll
            for (int j = 0; j < 4; j++) kv[j] = KV[(tc + 32 * j) * 65 + d];
#pragma unroll
            for (int i = 0; i < 4; i++)
#pragma unroll
                for (int j = 0; j < 4; j++) acc[i][j] += qv[i] * kv[j];
        }
#pragma unroll
        for (int i = 0; i < 4; i++)
#pragma unroll
            for (int j = 0; j < 4; j++)
                Ss[(tr * 4 + i) * LP + kk0 + tc + 32 * j] = acc[i][j] * inv_temper;
    }
    __syncthreads();

    {
        const int lane = tc;
        const unsigned char* mbase = mask + ((size_t)b * LSEQ + q0) * LSEQ;
#pragma unroll
        for (int i = 0; i < 4; i++) {
            int r = tr * 4 + i;
            float* srow = Ss + r * LP;
            const unsigned char* mr = mbase + (size_t)r * LSEQ;
            float m = NEG_INF;
            for (int c = lane; c < LSEQ; c += 32) {
                float v = srow[c];
                if (mr[c]) { v = NEG_INF; srow[c] = v; }
                m = fmaxf(m, v);
            }
#pragma unroll
            for (int o = 16; o > 0; o >>= 1) m = fmaxf(m, __shfl_xor_sync(0xffffffffu, m, o));
            float s = 0.0f;
            for (int c = lane; c < LSEQ; c += 32) {
                float p = __expf(srow[c] - m);
                srow[c] = p;
                s += p;
            }
#pragma unroll
            for (int o = 16; o > 0; o >>= 1) s += __shfl_xor_sync(0xffffffffu, s, o);
            float inv = 1.0f / s;
            float* arow = attn_out + (((size_t)(h * BATCH + b)) * LSEQ + q0 + r) * LSEQ;
            for (int c = lane; c < LSEQ; c += 32) {
                float p = srow[c] * inv;
                srow[c] = p;
                arow[c] = p;
            }
        }
    }
    __syncthreads();

    float oacc[4][2] = {};
    for (int kk0 = 0; kk0 < LSEQ; kk0 += TKC) {
        __syncthreads();
        {
            int lk = t >> 4;
            int c4 = (t & 15) << 2;
#pragma unroll
            for (int rep = 0; rep < 8; rep++) {
                int kkl = lk + rep * 16;
                float4 v = *(const float4*)(vs + ((size_t)(b * LSEQ + kk0 + kkl)) * 1024 + hd + c4);
                KV[kkl * 65 + c4 + 0] = v.x;
                KV[kkl * 65 + c4 + 1] = v.y;
                KV[kkl * 65 + c4 + 2] = v.z;
                KV[kkl * 65 + c4 + 3] = v.w;
            }
        }
        __syncthreads();
#pragma unroll 4
        for (int kk = 0; kk < TKC; kk++) {
            float pv[4], vv[2];
#pragma unroll
            for (int i = 0; i < 4; i++) pv[i] = Ss[(tr * 4 + i) * LP + kk0 + kk];
            vv[0] = KV[kk * 65 + tc];
            vv[1] = KV[kk * 65 + tc + 32];
#pragma unroll
            for (int i = 0; i < 4; i++) {
                oacc[i][0] += pv[i] * vv[0];
                oacc[i][1] += pv[i] * vv[1];
            }
        }
    }
#pragma unroll
    for (int i = 0; i < 4; i++) {
        size_t base = ((size_t)(b * LSEQ + q0 + tr * 4 + i)) * 1024 + hd;
        ctx[base + tc]      = oacc[i][0];
        ctx[base + tc + 32] = oacc[i][1];
    }
}

// ---------------------------------------------------------------------------
// In-place LayerNorm
// ---------------------------------------------------------------------------
__global__ void ln_kernel(float* __restrict__ y,
                          const float* __restrict__ gamma,
                          const float* __restrict__ beta) {
    __shared__ float red[18];
    const int row = blockIdx.x;
    const int t = threadIdx.x;
    float* p = y + (size_t)row * 1024;
    float v[4];
    float s = 0.0f, s2 = 0.0f;
#pragma unroll
    for (int j = 0; j < 4; j++) {
        v[j] = p[t + 256 * j];
        s += v[j];
        s2 += v[j] * v[j];
    }
#pragma unroll
    for (int o = 16; o > 0; o >>= 1) {
        s  += __shfl_xor_sync(0xffffffffu, s, o);
        s2 += __shfl_xor_sync(0xffffffffu, s2, o);
    }
    int warp = t >> 5, lane = t & 31;
    if (lane == 0) { red[warp] = s; red[8 + warp] = s2; }
    __syncthreads();
    if (t == 0) {
        float a = 0.0f, bsum = 0.0f;
#pragma unroll
        for (int w = 0; w < 8; w++) { a += red[w]; bsum += red[8 + w]; }
        red[16] = a; red[17] = bsum;
    }
    __syncthreads();
    float mean = red[16] * (1.0f / 1024.0f);
    float var  = red[17] * (1.0f / 1024.0f) - mean * mean;
    float inv  = rsqrtf(var + 1e-5f);
#pragma unroll
    for (int j = 0; j < 4; j++) {
        int c = t + 256 * j;
        p[c] = (v[j] - mean) * inv * gamma[c] + beta[c];
    }
}

// ---------------------------------------------------------------------------
// kernel_launch
// Inputs: q, k, v, attn_mask(bool), w_qs, w_ks, w_vs, proj_w, proj_b,
//         ln_gamma, ln_beta
// d_out: [outputs 8192*1024 f32][attns 128*1024*1024 f32]
// ---------------------------------------------------------------------------
extern "C" void kernel_launch(void* const* d_in, const int* in_sizes, int n_in,
                              void* d_out, int out_size) {
    const float* q      = (const float*)d_in[0];
    const float* k      = (const float*)d_in[1];
    const float* v      = (const float*)d_in[2];
    const unsigned char* mask = (const unsigned char*)d_in[3];
    const float* w_qs   = (const float*)d_in[4];
    const float* w_ks   = (const float*)d_in[5];
    const float* w_vs   = (const float*)d_in[6];
    const float* proj_w = (const float*)d_in[7];
    const float* proj_b = (const float*)d_in[8];
    const float* gamma  = (const float*)d_in[9];
    const float* beta   = (const float*)d_in[10];

    float* out = (float*)d_out;
    float* attn_out = out + (size_t)8192 * 1024;

    float* F = nullptr;  __nv_bfloat16* WB = nullptr;
    cudaGetSymbolAddress((void**)&F,  g_f32);
    cudaGetSymbolAddress((void**)&WB, g_wbf);

    float* QS  = F;
    float* KS  = F + (size_t)8  * M1;
    float* VS  = F + (size_t)16 * M1;
    float* CTX = F + (size_t)24 * M1;

    __nv_bfloat16* WQh = WB + 0 * M1; __nv_bfloat16* WQl = WB + 1 * M1;
    __nv_bfloat16* WKh = WB + 2 * M1; __nv_bfloat16* WKl = WB + 3 * M1;
    __nv_bfloat16* WVh = WB + 4 * M1; __nv_bfloat16* WVl = WB + 5 * M1;
    __nv_bfloat16* WPh = WB + 6 * M1; __nv_bfloat16* WPl = WB + 7 * M1;

    cudaFuncSetAttribute(gemm_mma_kernel<0>, cudaFuncAttributeMaxDynamicSharedMemorySize, GEMM_SMEM);
    cudaFuncSetAttribute(gemm_mma_kernel<1>, cudaFuncAttributeMaxDynamicSharedMemorySize, GEMM_SMEM);
    cudaFuncSetAttribute(attn_kernel, cudaFuncAttributeMaxDynamicSharedMemorySize, ATTN_SMEM);

    // weights -> bf16 hi/lo in [N,K] layout
    reshape_split_qkv<<<4096, 256>>>(w_qs, WQh, WQl);
    reshape_split_qkv<<<4096, 256>>>(w_ks, WKh, WKl);
    reshape_split_qkv<<<4096, 256>>>(w_vs, WVh, WVl);
    split_bf16_kernel<<<1024, 256>>>((const float4*)proj_w, (uint2*)WPh, (uint2*)WPl, 256 * 1024);

    const dim3 gg(8, 64);   // N blocks x M blocks

    // QKV projections (A = fp32 input, converted inline)
    gemm_mma_kernel<0><<<gg, 256, GEMM_SMEM>>>(q, WQh, WQl, QS, nullptr, nullptr);
    gemm_mma_kernel<0><<<gg, 256, GEMM_SMEM>>>(k, WKh, WKl, KS, nullptr, nullptr);
    gemm_mma_kernel<0><<<gg, 256, GEMM_SMEM>>>(v, WVh, WVl, VS, nullptr, nullptr);

    // fused attention (writes attn_out + CTX)
    attn_kernel<<<dim3(LSEQ / TQ, BATCH, NHEAD), 256, ATTN_SMEM>>>(QS, KS, VS, mask, attn_out, CTX);

    // output projection + bias + residual, then in-place LayerNorm
    gemm_mma_kernel<1><<<gg, 256, GEMM_SMEM>>>(CTX, WPh, WPl, out, proj_b, q);
    ln_kernel<<<8192, 256>>>(out, gamma, beta);
}

// round 13
// speedup vs baseline: 1.3840x; 1.0070x over previous
#include <cuda_runtime.h>
#include <cuda_bf16.h>
#include <math.h>
#include <stdint.h>

// Problem constants
#define BATCH 8
#define LSEQ  1024
#define DMODEL 1024
#define NHEAD 16
#define DK 64

// ---------------------------------------------------------------------------
// Scratch (__device__ globals; allocation APIs forbidden)
//   g_f32 : QS[8M] KS[8M] VS[8M] CTX[8M] floats
//   g_wbf : WQh WQl WKh WKl WVh WVl WPh WPl (1M bf16 each), [N,K] row-major
// ---------------------------------------------------------------------------
#define M1 (1024u*1024u)
__device__ float          g_f32[(size_t)32 * M1];
__device__ __nv_bfloat16  g_wbf[(size_t)8  * M1];

// ======================= helpers ===========================================
__device__ __forceinline__ uint32_t smem_u32(const void* p) {
    uint32_t a;
    asm("{ .reg .u64 t; cvta.to.shared.u64 t, %1; cvt.u32.u64 %0, t; }"
        : "=r"(a) : "l"(p));
    return a;
}
__device__ __forceinline__ void ldsm4(uint32_t* r, uint32_t addr) {
    asm volatile("ldmatrix.sync.aligned.m8n8.x4.shared.b16 {%0,%1,%2,%3}, [%4];"
                 : "=r"(r[0]), "=r"(r[1]), "=r"(r[2]), "=r"(r[3]) : "r"(addr));
}
__device__ __forceinline__ void mma16816(float* d, const uint32_t* a, const uint32_t* b) {
    asm volatile(
        "mma.sync.aligned.m16n8k16.row.col.f32.bf16.bf16.f32 "
        "{%0,%1,%2,%3}, {%4,%5,%6,%7}, {%8,%9}, {%0,%1,%2,%3};"
        : "+f"(d[0]), "+f"(d[1]), "+f"(d[2]), "+f"(d[3])
        : "r"(a[0]), "r"(a[1]), "r"(a[2]), "r"(a[3]), "r"(b[0]), "r"(b[1]));
}
// split 4 floats into packed bf16 hi (2x u32? -> 2 u32 of 2 bf16) and lo
__device__ __forceinline__ void split4(float4 v, uint32_t& h0, uint32_t& h1,
                                       uint32_t& l0, uint32_t& l1) {
    __nv_bfloat162 ha = __floats2bfloat162_rn(v.x, v.y);
    __nv_bfloat162 hb = __floats2bfloat162_rn(v.z, v.w);
    float lx = v.x - __bfloat162float(ha.x);
    float ly = v.y - __bfloat162float(ha.y);
    float lz = v.z - __bfloat162float(hb.x);
    float lw = v.w - __bfloat162float(hb.y);
    __nv_bfloat162 la = __floats2bfloat162_rn(lx, ly);
    __nv_bfloat162 lb = __floats2bfloat162_rn(lz, lw);
    h0 = (uint32_t)__bfloat16_as_ushort(ha.x) | ((uint32_t)__bfloat16_as_ushort(ha.y) << 16);
    h1 = (uint32_t)__bfloat16_as_ushort(hb.x) | ((uint32_t)__bfloat16_as_ushort(hb.y) << 16);
    l0 = (uint32_t)__bfloat16_as_ushort(la.x) | ((uint32_t)__bfloat16_as_ushort(la.y) << 16);
    l1 = (uint32_t)__bfloat16_as_ushort(lb.x) | ((uint32_t)__bfloat16_as_ushort(lb.y) << 16);
}

// ======================= weight prep kernels ================================
// w_qs[h][d][kk] -> B^T[n=h*64+kk][k=d] bf16 hi/lo
__global__ void reshape_split_qkv(const float* __restrict__ w,
                                  __nv_bfloat16* __restrict__ hi,
                                  __nv_bfloat16* __restrict__ lo) {
    int i = blockIdx.x * 256 + threadIdx.x;   // 1M elements
    int n = i >> 10;
    int d = i & 1023;
    float v = w[((n >> 6) << 16) + (d << 6) + (n & 63)];
    __nv_bfloat16 h = __float2bfloat16(v);
    hi[i] = h;
    lo[i] = __float2bfloat16(v - __bfloat162float(h));
}
// proj_w is already [N,K] row-major; plain split
__global__ void split_bf16_kernel(const float4* __restrict__ x,
                                  uint2* __restrict__ hi, uint2* __restrict__ lo, int n4) {
    int i = blockIdx.x * 256 + threadIdx.x;
    if (i >= n4) return;
    uint32_t h0, h1, l0, l1;
    split4(x[i], h0, h1, l0, l1);
    hi[i] = make_uint2(h0, h1);
    lo[i] = make_uint2(l0, l1);
}

// ======================= mma.sync split-bf16 GEMM ===========================
// C[8192,1024] = A[8192,1024](fp32, converted inline) * B^T (bf16 hi/lo [N,K])
// acc = Ah*Bh + Ah*Bl + Al*Bh.  CTA 128x128, K-chunk 32, double-buffered smem.
// EPI==1: += bias[col] + resid[row,col]
#define GSTRIDE 80                 // padded smem row stride (bytes)
#define TILE_B  (128 * GSTRIDE)    // 10240
#define STAGE_B (4 * TILE_B)       // Ah Al Bh Bl
#define GEMM_SMEM (2 * STAGE_B)    // 81920

template <int EPI>
__global__ __launch_bounds__(256, 1)
void gemm_mma_kernel(const float* __restrict__ A,
                     const __nv_bfloat16* __restrict__ Bh,
                     const __nv_bfloat16* __restrict__ Bl,
                     float* __restrict__ C,
                     const float* __restrict__ bias,
                     const float* __restrict__ resid) {
    extern __shared__ __align__(128) char sm[];
    const int t = threadIdx.x;
    const int bx = blockIdx.x, by = blockIdx.y;
    const int wid = t >> 5, lane = t & 31;

    const float* Abase = A + (size_t)(by * 128) * 1024;
    const __nv_bfloat16* Bhb = Bh + (size_t)(bx * 128) * 1024;
    const __nv_bfloat16* Blb = Bl + (size_t)(bx * 128) * 1024;

    float4 ar[4];
    uint4  bhr[2], blr[2];

    const uint32_t smb = smem_u32(sm);
    const int wm = wid & 3;      // M warp (4 x 32 rows)
    const int wn = wid >> 2;     // N warp (2 x 64 cols)

    float acc[2][8][4];
#pragma unroll
    for (int mt = 0; mt < 2; mt++)
#pragma unroll
        for (int nt = 0; nt < 8; nt++)
#pragma unroll
            for (int j = 0; j < 4; j++) acc[mt][nt][j] = 0.0f;

    // ldmatrix base byte-offsets (within tile, k-offset added later)
    const uint32_t aoff = (uint32_t)((wm * 32 + (lane & 15)) * GSTRIDE + (lane >> 4) * 16);
    const uint32_t boff = (uint32_t)((wn * 64 + (lane & 7) + ((lane >> 4) & 1) * 8) * GSTRIDE
                                     + ((lane >> 3) & 1) * 16);

#define LOAD_REGS(k0)                                                         \
    {                                                                         \
        _Pragma("unroll")                                                     \
        for (int i = 0; i < 4; i++) {                                         \
            int idx = t + 256 * i, row = idx >> 3, seg = idx & 7;             \
            ar[i] = *(const float4*)(Abase + (size_t)row * 1024 + (k0) + seg * 4); \
        }                                                                     \
        _Pragma("unroll")                                                     \
        for (int i = 0; i < 2; i++) {                                         \
            int idx = t + 256 * i, row = idx >> 2, seg = idx & 3;             \
            const char* ph = (const char*)(Bhb + (size_t)row * 1024 + (k0)) + seg * 16; \
            const char* pl = (const char*)(Blb + (size_t)row * 1024 + (k0)) + seg * 16; \
            bhr[i] = *(const uint4*)ph;                                       \
            blr[i] = *(const uint4*)pl;                                       \
        }                                                                     \
    }

#define STORE_SMEM(buf)                                                      \
    {                                                                         \
        char* AH = sm + (buf) * STAGE_B;                                      \
        char* AL = AH + TILE_B;                                               \
        char* BHs = AH + 2 * TILE_B;                                          \
        char* BLs = AH + 3 * TILE_B;                                          \
        _Pragma("unroll")                                                     \
        for (int i = 0; i < 4; i++) {                                         \
            int idx = t + 256 * i, row = idx >> 3, seg = idx & 7;             \
            uint32_t h0, h1, l0, l1;                                          \
            split4(ar[i], h0, h1, l0, l1);                                    \
            *(uint2*)(AH + row * GSTRIDE + seg * 8) = make_uint2(h0, h1);     \
            *(uint2*)(AL + row * GSTRIDE + seg * 8) = make_uint2(l0, l1);     \
        }                                                                     \
        _Pragma("unroll")                                                     \
        for (int i = 0; i < 2; i++) {                                         \
            int idx = t + 256 * i, row = idx >> 2, seg = idx & 3;             \
            *(uint4*)(BHs + row * GSTRIDE + seg * 16) = bhr[i];               \
            *(uint4*)(BLs + row * GSTRIDE + seg * 16) = blr[i];               \
        }                                                                     \
    }

    LOAD_REGS(0);
    STORE_SMEM(0);
    __syncthreads();

    for (int c = 0; c < 32; c++) {
        const int buf = c & 1;
        if (c + 1 < 32) LOAD_REGS((c + 1) * 32);

        const uint32_t AHb = smb + buf * STAGE_B;
        const uint32_t ALb = AHb + TILE_B;
        const uint32_t BHt = AHb + 2 * TILE_B;
        const uint32_t BLt = AHb + 3 * TILE_B;
#pragma unroll
        for (int ks = 0; ks < 2; ks++) {
            const uint32_t kb = ks * 32;
            uint32_t ah[2][4], al[2][4], bh[8][2], bl[8][2];
#pragma unroll
            for (int mt = 0; mt < 2; mt++) {
                ldsm4(ah[mt], AHb + aoff + mt * 16 * GSTRIDE + kb);
                ldsm4(al[mt], ALb + aoff + mt * 16 * GSTRIDE + kb);
            }
#pragma unroll
            for (int p = 0; p < 4; p++) {
                uint32_t r[4];
                ldsm4(r, BHt + boff + p * 16 * GSTRIDE + kb);
                bh[2 * p][0] = r[0]; bh[2 * p][1] = r[1];
                bh[2 * p + 1][0] = r[2]; bh[2 * p + 1][1] = r[3];
                ldsm4(r, BLt + boff + p * 16 * GSTRIDE + kb);
                bl[2 * p][0] = r[0]; bl[2 * p][1] = r[1];
                bl[2 * p + 1][0] = r[2]; bl[2 * p + 1][1] = r[3];
            }
#pragma unroll
            for (int mt = 0; mt < 2; mt++)
#pragma unroll
                for (int nt = 0; nt < 8; nt++) {
                    mma16816(acc[mt][nt], ah[mt], bh[nt]);
                    mma16816(acc[mt][nt], ah[mt], bl[nt]);
                    mma16816(acc[mt][nt], al[mt], bh[nt]);
                }
        }
        if (c + 1 < 32) {
            STORE_SMEM(buf ^ 1);
            __syncthreads();
        }
    }

    // epilogue: d frag mapping r0 = lane>>2 (+8), c0 = (lane&3)*2 (+1)
    const int r0 = lane >> 2, c0 = (lane & 3) * 2;
#pragma unroll
    for (int mt = 0; mt < 2; mt++)
#pragma unroll
        for (int nt = 0; nt < 8; nt++)
#pragma unroll
            for (int half = 0; half < 2; half++) {
                int row = by * 128 + wm * 32 + mt * 16 + r0 + half * 8;
                int col = bx * 128 + wn * 64 + nt * 8 + c0;
                float2 v = make_float2(acc[mt][nt][half * 2], acc[mt][nt][half * 2 + 1]);
                size_t idx = (size_t)row * 1024 + col;
                if (EPI) {
                    v.x += bias[col]     + resid[idx];
                    v.y += bias[col + 1] + resid[idx + 1];
                }
                *(float2*)(C + idx) = v;
            }
}

// ---------------------------------------------------------------------------
// Fused attention (unchanged from passing R9 kernel)
// ---------------------------------------------------------------------------
#define TQ 32
#define TKC 128
#define LP (LSEQ + 1)
#define ATTN_SMEM ((TQ * LP + TQ * DK + TKC * 65) * 4)

__global__ __launch_bounds__(256, 1)
void attn_kernel(const float* __restrict__ qs, const float* __restrict__ ks,
                 const float* __restrict__ vs, const unsigned char* __restrict__ mask,
                 float* __restrict__ attn_out, float* __restrict__ ctx) {
    extern __shared__ float smf[];
    float* Ss = smf;                   // TQ x LP
    float* Qs = Ss + TQ * LP;          // TQ x DK
    float* KV = Qs + TQ * DK;          // TKC x 65

    const int h = blockIdx.z, b = blockIdx.y;
    const int q0 = blockIdx.x * TQ;
    const int t = threadIdx.x;
    const int hd = h * DK;
    const float inv_temper = 1.0f / 32.0f;   // 1/sqrt(D_MODEL)
    const float NEG_INF = __int_as_float(0xff800000);

    {
        int r = t >> 4;
        int c4 = (t & 15) << 2;
#pragma unroll
        for (int rep = 0; rep < 2; rep++) {
            int rr = r + rep * 16;
            float4 v = *(const float4*)(qs + ((size_t)(b * LSEQ + q0 + rr)) * 1024 + hd + c4);
            *(float4*)&Qs[rr * DK + c4] = v;
        }
    }

    const int tr = t >> 5;
    const int tc = t & 31;

    for (int kk0 = 0; kk0 < LSEQ; kk0 += TKC) {
        __syncthreads();
        {
            int lk = t >> 4;
            int c4 = (t & 15) << 2;
#pragma unroll
            for (int rep = 0; rep < 8; rep++) {
                int kkl = lk + rep * 16;
                float4 v = *(const float4*)(ks + ((size_t)(b * LSEQ + kk0 + kkl)) * 1024 + hd + c4);
                KV[kkl * 65 + c4 + 0] = v.x;
                KV[kkl * 65 + c4 + 1] = v.y;
                KV[kkl * 65 + c4 + 2] = v.z;
                KV[kkl * 65 + c4 + 3] = v.w;
            }
        }
        __syncthreads();
        float acc[4][4] = {};
#pragma unroll
        for (int d = 0; d < DK; d++) {
            float qv[4], kv[4];
#pragma unroll
            for (int i = 0; i < 4; i++) qv[i] = Qs[(tr * 4 + i) * DK + d];
#pragma unroll
            for (int j = 0; j < 4; j++) kv[j] = KV[(tc + 32 * j) * 65 + d];
#pragma unroll
            for (int i = 0; i < 4; i++)
#pragma unroll
                for (int j = 0; j < 4; j++) acc[i][j] += qv[i] * kv[j];
        }
#pragma unroll
        for (int i = 0; i < 4; i++)
#pragma unroll
            for (int j = 0; j < 4; j++)
                Ss[(tr * 4 + i) * LP + kk0 + tc + 32 * j] = acc[i][j] * inv_temper;
    }
    __syncthreads();

    {
        const int lane = tc;
        const unsigned char* mbase = mask + ((size_t)b * LSEQ + q0) * LSEQ;
#pragma unroll
        for (int i = 0; i < 4; i++) {
            int r = tr * 4 + i;
            float* srow = Ss + r * LP;
            const unsigned char* mr = mbase + (size_t)r * LSEQ;
            float m = NEG_INF;
            for (int c = lane; c < LSEQ; c += 32) {
                float v = srow[c];
                if (mr[c]) { v = NEG_INF; srow[c] = v; }
                m = fmaxf(m, v);
            }
#pragma unroll
            for (int o = 16; o > 0; o >>= 1) m = fmaxf(m, __shfl_xor_sync(0xffffffffu, m, o));
            float s = 0.0f;
            for (int c = lane; c < LSEQ; c += 32) {
                float p = __expf(srow[c] - m);
                srow[c] = p;
                s += p;
            }
#pragma unroll
            for (int o = 16; o > 0; o >>= 1) s += __shfl_xor_sync(0xffffffffu, s, o);
            float inv = 1.0f / s;
            float* arow = attn_out + (((size_t)(h * BATCH + b)) * LSEQ + q0 + r) * LSEQ;
            for (int c = lane; c < LSEQ; c += 32) {
                float p = srow[c] * inv;
                srow[c] = p;
                arow[c] = p;
            }
        }
    }
    __syncthreads();

    float oacc[4][2] = {};
    for (int kk0 = 0; kk0 < LSEQ; kk0 += TKC) {
        __syncthreads();
        {
            int lk = t >> 4;
            int c4 = (t & 15) << 2;
#pragma unroll
            for (int rep = 0; rep < 8; rep++) {
                int kkl = lk + rep * 16;
                float4 v = *(const float4*)(vs + ((size_t)(b * LSEQ + kk0 + kkl)) * 1024 + hd + c4);
                KV[kkl * 65 + c4 + 0] = v.x;
                KV[kkl * 65 + c4 + 1] = v.y;
                KV[kkl * 65 + c4 + 2] = v.z;
                KV[kkl * 65 + c4 + 3] = v.w;
            }
        }
        __syncthreads();
#pragma unroll 4
        for (int kk = 0; kk < TKC; kk++) {
            float pv[4], vv[2];
#pragma unroll
            for (int i = 0; i < 4; i++) pv[i] = Ss[(tr * 4 + i) * LP + kk0 + kk];
            vv[0] = KV[kk * 65 + tc];
            vv[1] = KV[kk * 65 + tc + 32];
#pragma unroll
            for (int i = 0; i < 4; i++) {
                oacc[i][0] += pv[i] * vv[0];
                oacc[i][1] += pv[i] * vv[1];
            }
        }
    }
#pragma unroll
    for (int i = 0; i < 4; i++) {
        size_t base = ((size_t)(b * LSEQ + q0 + tr * 4 + i)) * 1024 + hd;
        ctx[base + tc]      = oacc[i][0];
        ctx[base + tc + 32] = oacc[i][1];
    }
}

// ---------------------------------------------------------------------------
// In-place LayerNorm
// ---------------------------------------------------------------------------
__global__ void ln_kernel(float* __restrict__ y,
                          const float* __restrict__ gamma,
                          const float* __restrict__ beta) {
    __shared__ float red[18];
    const int row = blockIdx.x;
    const int t = threadIdx.x;
    float* p = y + (size_t)row * 1024;
    float v[4];
    float s = 0.0f, s2 = 0.0f;
#pragma unroll
    for (int j = 0; j < 4; j++) {
        v[j] = p[t + 256 * j];
        s += v[j];
        s2 += v[j] * v[j];
    }
#pragma unroll
    for (int o = 16; o > 0; o >>= 1) {
        s  += __shfl_xor_sync(0xffffffffu, s, o);
        s2 += __shfl_xor_sync(0xffffffffu, s2, o);
    }
    int warp = t >> 5, lane = t & 31;
    if (lane == 0) { red[warp] = s; red[8 + warp] = s2; }
    __syncthreads();
    if (t == 0) {
        float a = 0.0f, bsum = 0.0f;
#pragma unroll
        for (int w = 0; w < 8; w++) { a += red[w]; bsum += red[8 + w]; }
        red[16] = a; red[17] = bsum;
    }
    __syncthreads();
    float mean = red[16] * (1.0f / 1024.0f);
    float var  = red[17] * (1.0f / 1024.0f) - mean * mean;
    float inv  = rsqrtf(var + 1e-5f);
#pragma unroll
    for (int j = 0; j < 4; j++) {
        int c = t + 256 * j;
        p[c] = (v[j] - mean) * inv * gamma[c] + beta[c];
    }
}

// ---------------------------------------------------------------------------
// kernel_launch
// Inputs: q, k, v, attn_mask(bool), w_qs, w_ks, w_vs, proj_w, proj_b,
//         ln_gamma, ln_beta
// d_out: [outputs 8192*1024 f32][attns 128*1024*1024 f32]
// ---------------------------------------------------------------------------
extern "C" void kernel_launch(void* const* d_in, const int* in_sizes, int n_in,
                              void* d_out, int out_size) {
    const float* q      = (const float*)d_in[0];
    const float* k      = (const float*)d_in[1];
    const float* v      = (const float*)d_in[2];
    const unsigned char* mask = (const unsigned char*)d_in[3];
    const float* w_qs   = (const float*)d_in[4];
    const float* w_ks   = (const float*)d_in[5];
    const float* w_vs   = (const float*)d_in[6];
    const float* proj_w = (const float*)d_in[7];
    const float* proj_b = (const float*)d_in[8];
    const float* gamma  = (const float*)d_in[9];
    const float* beta   = (const float*)d_in[10];

    float* out = (float*)d_out;
    float* attn_out = out + (size_t)8192 * 1024;

    float* F = nullptr;  __nv_bfloat16* WB = nullptr;
    cudaGetSymbolAddress((void**)&F,  g_f32);
    cudaGetSymbolAddress((void**)&WB, g_wbf);

    float* QS  = F;
    float* KS  = F + (size_t)8  * M1;
    float* VS  = F + (size_t)16 * M1;
    float* CTX = F + (size_t)24 * M1;

    __nv_bfloat16* WQh = WB + 0 * M1; __nv_bfloat16* WQl = WB + 1 * M1;
    __nv_bfloat16* WKh = WB + 2 * M1; __nv_bfloat16* WKl = WB + 3 * M1;
    __nv_bfloat16* WVh = WB + 4 * M1; __nv_bfloat16* WVl = WB + 5 * M1;
    __nv_bfloat16* WPh = WB + 6 * M1; __nv_bfloat16* WPl = WB + 7 * M1;

    cudaFuncSetAttribute(gemm_mma_kernel<0>, cudaFuncAttributeMaxDynamicSharedMemorySize, GEMM_SMEM);
    cudaFuncSetAttribute(gemm_mma_kernel<1>, cudaFuncAttributeMaxDynamicSharedMemorySize, GEMM_SMEM);
    cudaFuncSetAttribute(attn_kernel, cudaFuncAttributeMaxDynamicSharedMemorySize, ATTN_SMEM);

    // weights -> bf16 hi/lo in [N,K] layout
    reshape_split_qkv<<<4096, 256>>>(w_qs, WQh, WQl);
    reshape_split_qkv<<<4096, 256>>>(w_ks, WKh, WKl);
    reshape_split_qkv<<<4096, 256>>>(w_vs, WVh, WVl);
    split_bf16_kernel<<<1024, 256>>>((const float4*)proj_w, (uint2*)WPh, (uint2*)WPl, 256 * 1024);

    const dim3 gg(8, 64);   // N blocks x M blocks

    // QKV projections (A = fp32 input, converted inline)
    gemm_mma_kernel<0><<<gg, 256, GEMM_SMEM>>>(q, WQh, WQl, QS, nullptr, nullptr);
    gemm_mma_kernel<0><<<gg, 256, GEMM_SMEM>>>(k, WKh, WKl, KS, nullptr, nullptr);
    gemm_mma_kernel<0><<<gg, 256, GEMM_SMEM>>>(v, WVh, WVl, VS, nullptr, nullptr);

    // fused attention (writes attn_out + CTX)
    attn_kernel<<<dim3(LSEQ / TQ, BATCH, NHEAD), 256, ATTN_SMEM>>>(QS, KS, VS, mask, attn_out, CTX);

    // output projection + bias + residual, then in-place LayerNorm
    gemm_mma_kernel<1><<<gg, 256, GEMM_SMEM>>>(CTX, WPh, WPl, out, proj_b, q);
    ln_kernel<<<8192, 256>>>(out, gamma, beta);
}